// round 1
// baseline (speedup 1.0000x reference)
#include <cuda_runtime.h>
#include <cuda_bf16.h>

#define CC 512      // channels
#define DD 512      // context dim
#define BB 8        // batch
#define HWN 16384   // H*W
#define TPOS 32     // spatial positions per tile in fused kernel
#define NT (HWN / TPOS)   // 512 tiles per batch
#define STRIDE 33   // smem row stride (bank-conflict free)
#define SCALE_C 0.04419417382415922f  // 512^-0.5

// Scratch (device globals; no allocations allowed)
__device__ float g_qk[BB * CC];              // scale * (q @ Wk)
__device__ float g_pooled[BB * NT * CC];     // per-tile unnormalized weighted sums
__device__ float g_m[BB * NT];               // per-tile logit max
__device__ float g_z[BB * NT];               // per-tile sum exp(l - m)
__device__ float g_gate[BB * CC];            // final channel gates

// ---------------------------------------------------------------------------
// k0: per batch b: q[o] = ctx[b]·Wq[o,:] + bq[o];  qk[c] = SCALE * sum_o q[o]*Wk[o,c]
// ---------------------------------------------------------------------------
__global__ void __launch_bounds__(512) k0_qk(const float* __restrict__ ctx,
                                             const float* __restrict__ Wq,
                                             const float* __restrict__ bq,
                                             const float* __restrict__ Wk) {
    __shared__ float ctxs[DD];
    __shared__ float qs[CC];
    int b = blockIdx.x, tid = threadIdx.x;
    int lane = tid & 31, warp = tid >> 5;   // 16 warps

    ctxs[tid] = ctx[b * DD + tid];
    __syncthreads();

    // warp-per-output GEMV: q = ctx @ Wq^T + bq
    for (int o = warp; o < CC; o += 16) {
        float a = 0.f;
        #pragma unroll
        for (int j = lane; j < DD; j += 32) a += Wq[o * DD + j] * ctxs[j];
        #pragma unroll
        for (int off = 16; off; off >>= 1) a += __shfl_xor_sync(0xffffffffu, a, off);
        if (lane == 0) qs[o] = a + bq[o];
    }
    __syncthreads();

    // qk[c] = SCALE * sum_o qs[o] * Wk[o*CC + c]   (coalesced over c)
    int c = tid;
    float a = 0.f;
    #pragma unroll 8
    for (int o = 0; o < CC; o++) a += qs[o] * Wk[o * CC + c];
    g_qk[b * CC + c] = a * SCALE_C;
}

// ---------------------------------------------------------------------------
// k1: fused logits + flash-style partial softmax + weighted pooling.
// Grid: (NT, BB), 512 threads. Each block handles a 512-ch x 32-pos tile of x
// cached in SMEM (read x from HBM exactly once here).
// ---------------------------------------------------------------------------
__global__ void __launch_bounds__(512) k1_fused(const float* __restrict__ x) {
    extern __shared__ float xs[];          // [CC][STRIDE] = 512*33 floats
    __shared__ float qks[CC];
    __shared__ float part[512];
    __shared__ float lw[TPOS];             // logits -> weights

    int tile = blockIdx.x, b = blockIdx.y;
    int tid = threadIdx.x;
    int base = b * (CC * HWN) + tile * TPOS;

    qks[tid] = g_qk[b * CC + tid];

    // Load tile: 512 channels x 32 floats = 4096 float4, 8 per thread
    #pragma unroll
    for (int k = 0; k < 8; k++) {
        int idx = tid + k * 512;       // 0..4095
        int c = idx >> 3;              // 8 float4 per channel row
        int v = idx & 7;
        float4 d = *(const float4*)(x + base + c * HWN + v * 4);
        float* dst = xs + c * STRIDE + v * 4;
        dst[0] = d.x; dst[1] = d.y; dst[2] = d.z; dst[3] = d.w;
    }
    __syncthreads();

    // Partial logits: thread (cg,t) sums 32 channels for position t
    int t  = tid & 31;
    int cg = tid >> 5;                 // 0..15
    {
        const float* row = xs + (cg * 32) * STRIDE + t;
        const float* qrow = qks + cg * 32;
        float acc = 0.f;
        #pragma unroll 8
        for (int c = 0; c < 32; c++) acc += qrow[c] * row[c * STRIDE];
        part[tid] = acc;
    }
    __syncthreads();

    // Warp 0: finish logits, local softmax stats
    if (tid < 32) {
        float l = 0.f;
        #pragma unroll
        for (int g = 0; g < 16; g++) l += part[g * 32 + tid];
        float m = l;
        #pragma unroll
        for (int off = 16; off; off >>= 1) m = fmaxf(m, __shfl_xor_sync(0xffffffffu, m, off));
        float w = __expf(l - m);
        float z = w;
        #pragma unroll
        for (int off = 16; off; off >>= 1) z += __shfl_xor_sync(0xffffffffu, z, off);
        lw[tid] = w;
        if (tid == 0) {
            int blk = b * NT + tile;
            g_m[blk] = m;
            g_z[blk] = z;
        }
    }
    __syncthreads();

    // Pooled partial: thread c sums w[t]*x[c][t] over the tile
    {
        int c = tid;
        const float* row = xs + c * STRIDE;
        float p = 0.f;
        #pragma unroll 8
        for (int tt = 0; tt < TPOS; tt++) p += lw[tt] * row[tt];
        g_pooled[(b * NT + tile) * CC + c] = p;
    }
}

// ---------------------------------------------------------------------------
// k2: per batch: combine NT=512 partials (global max, Z, pooled), then
// gate = Wv @ pooled_norm + bv.  Grid: (BB), 1024 threads.
// ---------------------------------------------------------------------------
__global__ void __launch_bounds__(1024) k2_combine(const float* __restrict__ Wv,
                                                   const float* __restrict__ bv) {
    __shared__ float sc[NT];        // e^(m_i - M)
    __shared__ float pooled[CC];
    __shared__ float pool2[CC];
    __shared__ float red[32];
    __shared__ float s_M, s_Z;

    int b = blockIdx.x, tid = threadIdx.x;
    int lane = tid & 31, warp = tid >> 5;   // 32 warps

    // Global max over 512 tile maxima (one per thread for tid<512)
    float m = (tid < NT) ? g_m[b * NT + tid] : -1e30f;
    float mw = m;
    #pragma unroll
    for (int off = 16; off; off >>= 1) mw = fmaxf(mw, __shfl_xor_sync(0xffffffffu, mw, off));
    if (lane == 0) red[warp] = mw;
    __syncthreads();
    if (warp == 0) {
        float v = red[lane];
        #pragma unroll
        for (int off = 16; off; off >>= 1) v = fmaxf(v, __shfl_xor_sync(0xffffffffu, v, off));
        if (lane == 0) s_M = v;
    }
    __syncthreads();
    float M = s_M;

    float e = (tid < NT) ? __expf(m - M) : 0.f;
    if (tid < NT) sc[tid] = e;
    float zt = (tid < NT) ? g_z[b * NT + tid] * e : 0.f;
    #pragma unroll
    for (int off = 16; off; off >>= 1) zt += __shfl_xor_sync(0xffffffffu, zt, off);
    if (lane == 0) red[warp] = zt;
    __syncthreads();
    if (warp == 0) {
        float v = red[lane];
        #pragma unroll
        for (int off = 16; off; off >>= 1) v += __shfl_xor_sync(0xffffffffu, v, off);
        if (lane == 0) s_Z = v;
    }
    __syncthreads();

    // Pooled combine: 1024 threads, (c, half) layout — each handles 256 tiles
    int c = tid & (CC - 1);
    int half = tid >> 9;
    {
        const float* pp = g_pooled + (b * NT + half * (NT / 2)) * CC + c;
        const float* ss = sc + half * (NT / 2);
        float acc = 0.f;
        #pragma unroll 8
        for (int i = 0; i < NT / 2; i++) acc += pp[i * CC] * ss[i];
        if (half) pool2[c] = acc;
        __syncthreads();
        if (!half) pooled[c] = (acc + pool2[c]) * (1.f / s_Z);
    }
    __syncthreads();

    // gate = Wv @ pooled + bv : warp-per-output GEMV, 32 warps x 16 outputs
    for (int o = warp; o < CC; o += 32) {
        float a = 0.f;
        #pragma unroll
        for (int j = lane; j < CC; j += 32) a += Wv[o * CC + j] * pooled[j];
        #pragma unroll
        for (int off = 16; off; off >>= 1) a += __shfl_xor_sync(0xffffffffu, a, off);
        if (lane == 0) g_gate[b * CC + o] = a + bv[o];
    }
}

// ---------------------------------------------------------------------------
// k3: out = x * gate[b,c]  (float4 streaming, 1.07 GB traffic)
// ---------------------------------------------------------------------------
__global__ void __launch_bounds__(512) k3_scale(const float4* __restrict__ x,
                                                float4* __restrict__ out) {
    int i = blockIdx.x * 512 + threadIdx.x;     // float4 index, total 16777216
    float g = g_gate[i >> 12];                  // (i*4)/16384
    float4 d = x[i];
    d.x *= g; d.y *= g; d.z *= g; d.w *= g;
    out[i] = d;
}

// ---------------------------------------------------------------------------
extern "C" void kernel_launch(void* const* d_in, const int* in_sizes, int n_in,
                              void* d_out, int out_size) {
    const float* x   = (const float*)d_in[0];
    const float* ctx = (const float*)d_in[1];
    const float* Wq  = (const float*)d_in[2];
    const float* bq  = (const float*)d_in[3];
    const float* Wk  = (const float*)d_in[4];
    // d_in[5] = bk: constant shift of logits per batch -> cancels in softmax
    const float* Wv  = (const float*)d_in[6];
    const float* bv  = (const float*)d_in[7];

    const int smem1 = CC * STRIDE * sizeof(float);   // 67584 B
    cudaFuncSetAttribute(k1_fused, cudaFuncAttributeMaxDynamicSharedMemorySize, smem1);

    k0_qk<<<BB, 512>>>(ctx, Wq, bq, Wk);
    k1_fused<<<dim3(NT, BB), 512, smem1>>>(x);
    k2_combine<<<BB, 1024>>>(Wv, bv);
    k3_scale<<<(BB * CC * HWN) / (4 * 512), 512>>>((const float4*)x, (float4*)d_out);
}

// round 2
// speedup vs baseline: 1.6155x; 1.6155x over previous
#include <cuda_runtime.h>
#include <cuda_bf16.h>

#define CC 512      // channels
#define DD 512      // context dim
#define BB 8        // batch
#define HWN 16384   // H*W
#define TPOS 16     // spatial positions per tile in fused kernel
#define NT (HWN / TPOS)   // 1024 tiles per batch
#define STRIDE 17   // smem row stride (bank-conflict free-ish)
#define SCALE_C 0.04419417382415922f  // 512^-0.5

// Scratch (device globals; no allocations allowed)
__device__ float g_q[BB * CC];               // SCALE * (ctx @ Wq^T + bq)
__device__ float g_qk[BB * CC];              // SCALE * (q @ Wk)
__device__ float g_pooled[BB * NT * CC];     // per-tile unnormalized weighted sums
__device__ float g_m[BB * NT];               // per-tile logit max
__device__ float g_z[BB * NT];               // per-tile sum exp(l - m)
__device__ float g_sc[BB * NT];              // e^(m_t - M) / Z
__device__ float g_pp[BB * 8 * CC];          // t-chunk partial pooled
__device__ float g_gate[BB * CC];            // final channel gates

// ---------------------------------------------------------------------------
// k0a: q_scaled[b][o] = SCALE * (ctx[b]·Wq[o,:] + bq[o]).  Grid (64, BB), 256t.
// ---------------------------------------------------------------------------
__global__ void __launch_bounds__(256) k0a_q(const float* __restrict__ ctx,
                                             const float* __restrict__ Wq,
                                             const float* __restrict__ bq) {
    __shared__ float ctxs[DD];
    int b = blockIdx.y, tid = threadIdx.x;
    int lane = tid & 31, warp = tid >> 5;      // 8 warps
    ctxs[tid] = ctx[b * DD + tid];
    ctxs[tid + 256] = ctx[b * DD + tid + 256];
    __syncthreads();
    int o = blockIdx.x * 8 + warp;
    float a = 0.f;
    #pragma unroll
    for (int j = lane; j < DD; j += 32) a += Wq[o * DD + j] * ctxs[j];
    #pragma unroll
    for (int off = 16; off; off >>= 1) a += __shfl_xor_sync(0xffffffffu, a, off);
    if (lane == 0) g_q[b * CC + o] = (a + bq[o]) * SCALE_C;
}

// ---------------------------------------------------------------------------
// k0b: qk[b][c] = sum_o q_s[b][o] * Wk[o][c].  Grid (8 cchunks, BB), 256t.
// ---------------------------------------------------------------------------
__global__ void __launch_bounds__(256) k0b_qk(const float* __restrict__ Wk) {
    __shared__ float qs[CC];
    __shared__ float red[4][64];
    int b = blockIdx.y, tid = threadIdx.x;
    qs[tid] = g_q[b * CC + tid];
    qs[tid + 256] = g_q[b * CC + tid + 256];
    __syncthreads();
    int cl = tid & 63, og = tid >> 6;          // 4 o-groups of 128
    int c = blockIdx.x * 64 + cl;
    float a = 0.f;
    int o0 = og * 128;
    #pragma unroll 8
    for (int o = 0; o < 128; o++) a += qs[o0 + o] * Wk[(o0 + o) * CC + c];
    red[og][cl] = a;
    __syncthreads();
    if (og == 0) g_qk[b * CC + c] = red[0][cl] + red[1][cl] + red[2][cl] + red[3][cl];
}

// ---------------------------------------------------------------------------
// k1: fused logits + flash partial softmax + weighted pooling.
// Grid (NT, BB), 256 threads, 512ch x 16pos tile in smem (~38KB -> 6 CTA/SM).
// ---------------------------------------------------------------------------
__global__ void __launch_bounds__(256) k1_fused(const float* __restrict__ x) {
    __shared__ float xs[CC * STRIDE];
    __shared__ float qks[CC];
    __shared__ float part[256];
    __shared__ float lw[TPOS];

    int tile = blockIdx.x, b = blockIdx.y;
    int tid = threadIdx.x;
    long base = (long)b * (CC * HWN) + tile * TPOS;

    qks[tid] = g_qk[b * CC + tid];
    qks[tid + 256] = g_qk[b * CC + tid + 256];

    // Load tile: 512 ch x 16 floats = 2048 float4, 8 per thread
    #pragma unroll
    for (int k = 0; k < 8; k++) {
        int idx = tid + k * 256;        // 0..2047
        int c = idx >> 2;               // 4 float4 per channel row
        int v = idx & 3;
        float4 d = __ldcs((const float4*)(x + base + (long)c * HWN + v * 4));
        float* dst = xs + c * STRIDE + v * 4;
        dst[0] = d.x; dst[1] = d.y; dst[2] = d.z; dst[3] = d.w;
    }
    __syncthreads();

    // Partial logits: thread (cg,t), cg=tid>>4 (16 groups), t=tid&15
    {
        int t = tid & 15;
        int cg = tid >> 4;
        const float* row = xs + (cg * 32) * STRIDE + t;
        const float* qrow = qks + cg * 32;
        float acc = 0.f;
        #pragma unroll 8
        for (int c = 0; c < 32; c++) acc += qrow[c] * row[c * STRIDE];
        part[cg * 16 + t] = acc;
    }
    __syncthreads();

    // Warp 0: finish logits, local softmax stats (16-lane butterfly, halves mirror)
    if (tid < 32) {
        int t = tid & 15;
        float l = 0.f;
        #pragma unroll
        for (int g = 0; g < 16; g++) l += part[g * 16 + t];
        float m = l;
        #pragma unroll
        for (int off = 8; off; off >>= 1) m = fmaxf(m, __shfl_xor_sync(0xffffffffu, m, off));
        float w = __expf(l - m);
        float z = w;
        #pragma unroll
        for (int off = 8; off; off >>= 1) z += __shfl_xor_sync(0xffffffffu, z, off);
        if (tid < 16) lw[t] = w;
        if (tid == 0) {
            int blk = b * NT + tile;
            g_m[blk] = m;
            g_z[blk] = z;
        }
    }
    __syncthreads();

    // Pooled partial: each thread 2 channels
    float w0[TPOS];
    #pragma unroll
    for (int t = 0; t < TPOS; t++) w0[t] = lw[t];
    #pragma unroll
    for (int h = 0; h < 2; h++) {
        int c = tid + h * 256;
        const float* row = xs + c * STRIDE;
        float p = 0.f;
        #pragma unroll
        for (int t = 0; t < TPOS; t++) p += w0[t] * row[t];
        g_pooled[(long)(b * NT + tile) * CC + c] = p;
    }
}

// ---------------------------------------------------------------------------
// k2a: per batch: global M, Z over NT=1024 tiles; sc[t] = e^(m-M)/Z.  Grid BB, 1024t.
// ---------------------------------------------------------------------------
__global__ void __launch_bounds__(1024) k2a_stats() {
    __shared__ float red[32];
    __shared__ float s_M, s_Z;
    int b = blockIdx.x, tid = threadIdx.x;
    int lane = tid & 31, warp = tid >> 5;

    float m = g_m[b * NT + tid];
    float mw = m;
    #pragma unroll
    for (int off = 16; off; off >>= 1) mw = fmaxf(mw, __shfl_xor_sync(0xffffffffu, mw, off));
    if (lane == 0) red[warp] = mw;
    __syncthreads();
    if (warp == 0) {
        float v = red[lane];
        #pragma unroll
        for (int off = 16; off; off >>= 1) v = fmaxf(v, __shfl_xor_sync(0xffffffffu, v, off));
        if (lane == 0) s_M = v;
    }
    __syncthreads();
    float e = __expf(m - s_M);
    float zt = g_z[b * NT + tid] * e;
    #pragma unroll
    for (int off = 16; off; off >>= 1) zt += __shfl_xor_sync(0xffffffffu, zt, off);
    if (lane == 0) red[warp] = zt;
    __syncthreads();
    if (warp == 0) {
        float v = red[lane];
        #pragma unroll
        for (int off = 16; off; off >>= 1) v += __shfl_xor_sync(0xffffffffu, v, off);
        if (lane == 0) s_Z = v;
    }
    __syncthreads();
    g_sc[b * NT + tid] = e * (1.f / s_Z);
}

// ---------------------------------------------------------------------------
// k2b: partial pooled combine over t-chunks.  Grid (4 cchunk, 8 tchunk, BB), 128t.
// ---------------------------------------------------------------------------
__global__ void __launch_bounds__(128) k2b_combine() {
    int cc = blockIdx.x, tc = blockIdx.y, b = blockIdx.z;
    int c = cc * 128 + threadIdx.x;
    int t0 = tc * 128;
    float acc = 0.f;
    const float* pp = g_pooled + (long)(b * NT + t0) * CC + c;
    const float* ss = g_sc + b * NT + t0;
    #pragma unroll 8
    for (int i = 0; i < 128; i++) acc += pp[(long)i * CC] * ss[i];
    g_pp[(b * 8 + tc) * CC + c] = acc;
}

// ---------------------------------------------------------------------------
// k2c: pooled = sum t-chunks; gate = Wv @ pooled + bv.  Grid (64, BB), 256t.
// ---------------------------------------------------------------------------
__global__ void __launch_bounds__(256) k2c_gate(const float* __restrict__ Wv,
                                                const float* __restrict__ bv) {
    __shared__ float pooled[CC];
    int b = blockIdx.y, tid = threadIdx.x;
    int lane = tid & 31, warp = tid >> 5;
    #pragma unroll
    for (int h = 0; h < 2; h++) {
        int c = tid + h * 256;
        float a = 0.f;
        #pragma unroll
        for (int j = 0; j < 8; j++) a += g_pp[(b * 8 + j) * CC + c];
        pooled[c] = a;
    }
    __syncthreads();
    int o = blockIdx.x * 8 + warp;
    float a = 0.f;
    #pragma unroll
    for (int j = lane; j < CC; j += 32) a += Wv[o * CC + j] * pooled[j];
    #pragma unroll
    for (int off = 16; off; off >>= 1) a += __shfl_xor_sync(0xffffffffu, a, off);
    if (lane == 0) g_gate[b * CC + o] = a + bv[o];
}

// ---------------------------------------------------------------------------
// k3: out = x * gate[b,c]  (float4 streaming, .cs hints)
// ---------------------------------------------------------------------------
__global__ void __launch_bounds__(512) k3_scale(const float4* __restrict__ x,
                                                float4* __restrict__ out) {
    int i = blockIdx.x * 512 + threadIdx.x;     // float4 index
    float g = g_gate[i >> 12];                  // 4096 float4 per (b,c)
    float4 d = __ldcs(x + i);
    d.x *= g; d.y *= g; d.z *= g; d.w *= g;
    __stcs(out + i, d);
}

// ---------------------------------------------------------------------------
extern "C" void kernel_launch(void* const* d_in, const int* in_sizes, int n_in,
                              void* d_out, int out_size) {
    const float* x   = (const float*)d_in[0];
    const float* ctx = (const float*)d_in[1];
    const float* Wq  = (const float*)d_in[2];
    const float* bq  = (const float*)d_in[3];
    const float* Wk  = (const float*)d_in[4];
    // d_in[5] = bk: constant logit shift per batch -> cancels in softmax
    const float* Wv  = (const float*)d_in[6];
    const float* bv  = (const float*)d_in[7];

    k0a_q<<<dim3(64, BB), 256>>>(ctx, Wq, bq);
    k0b_qk<<<dim3(8, BB), 256>>>(Wk);
    k1_fused<<<dim3(NT, BB), 256>>>(x);
    k2a_stats<<<BB, 1024>>>();
    k2b_combine<<<dim3(4, 8, BB), 128>>>();
    k2c_gate<<<dim3(64, BB), 256>>>(Wv, bv);
    k3_scale<<<(BB * CC * HWN) / (4 * 512), 512>>>((const float4*)x, (float4*)d_out);
}